// round 14
// baseline (speedup 1.0000x reference)
#include <cuda_runtime.h>
#include <math.h>

// Net_43490838839931: batched RK4 of ds/dt = MLP([s,u]) with 2->4->1 LeakyReLU net.
// R8: R7's scalar sign-specialized math (FADD ±|src| modifiers, 40 slots/el-step),
// but 2 elements/thread instead of 4: doubles warp count (2048 warps, 3.46/SMSP)
// to cover stalls; per-warp ILP (2 chains) still sufficient (~1.05 IPC demand).
//   g_j(s) = R_j*s + D_j ; stage2/3: fma(k, 0.5R_j, g_j) ; stage4: fma(k3, R_j, g_j)
//   dyn = lin + sum_j sign(w2_j)*|g_j|

#define NSTEPS 100

struct Uni {
    float R0, R1, R2, R3;      // q_j * w1a_j
    float hR0, hR1, hR2, hR3;  // 0.5 * R_j
    float P, hP;               // sum p_j*w1a_j, half of it
};

struct El {                    // per-element state
    float Qt, D0, D1, D2, D3, s;
};

template <int SGN>
__device__ __forceinline__ float dynsum(float g0, float g1, float g2, float g3,
                                        float lin) {
    // FADD with ±|src| modifiers — abs and sign are free in SASS.
    float A0 = (SGN & 1) ? -fabsf(g0) : fabsf(g0);
    float A1 = (SGN & 2) ? -fabsf(g1) : fabsf(g1);
    float A2 = (SGN & 4) ? -fabsf(g2) : fabsf(g2);
    float A3 = (SGN & 8) ? -fabsf(g3) : fabsf(g3);
    return lin + ((A0 + A1) + (A2 + A3));
}

template <int SGN>
__device__ __forceinline__ void step1(const Uni& U, El& e) {
    // stage 1 at s
    float g0 = fmaf(e.s, U.R0, e.D0);
    float g1 = fmaf(e.s, U.R1, e.D1);
    float g2 = fmaf(e.s, U.R2, e.D2);
    float g3 = fmaf(e.s, U.R3, e.D3);
    float lin1 = fmaf(U.P, e.s, e.Qt);
    float k1 = dynsum<SGN>(g0, g1, g2, g3, lin1);
    // stage 2 at s + 0.5*k1 (incremental)
    float h0 = fmaf(k1, U.hR0, g0);
    float h1 = fmaf(k1, U.hR1, g1);
    float h2 = fmaf(k1, U.hR2, g2);
    float h3 = fmaf(k1, U.hR3, g3);
    float lin2 = fmaf(k1, U.hP, lin1);
    float k2 = dynsum<SGN>(h0, h1, h2, h3, lin2);
    // stage 3 at s + 0.5*k2
    float m0 = fmaf(k2, U.hR0, g0);
    float m1 = fmaf(k2, U.hR1, g1);
    float m2 = fmaf(k2, U.hR2, g2);
    float m3 = fmaf(k2, U.hR3, g3);
    float lin3 = fmaf(k2, U.hP, lin1);
    float k3 = dynsum<SGN>(m0, m1, m2, m3, lin3);
    // stage 4 at s + k3
    float n0 = fmaf(k3, U.R0, g0);
    float n1 = fmaf(k3, U.R1, g1);
    float n2 = fmaf(k3, U.R2, g2);
    float n3 = fmaf(k3, U.R3, g3);
    float lin4 = fmaf(k3, U.P, lin1);
    float k4 = dynsum<SGN>(n0, n1, n2, n3, lin4);
    // combine
    float t = k2 + k3;
    float w = k1 + k4;
    float sum = fmaf(2.0f, t, w);
    e.s = fmaf(sum, 0.16666667f, e.s);
}

template <int SGN>
__device__ __forceinline__ void run_loop(const Uni& U, El (&E)[2], float2 xv,
                                         float4* o0, float4* o1) {
    float4 w0, w1;
    // Group 0: t=0 is the initial state, then 3 steps.
    w0.x = xv.x; w1.x = xv.y;
    step1<SGN>(U, E[0]); step1<SGN>(U, E[1]);
    w0.y = E[0].s; w1.y = E[1].s;
    step1<SGN>(U, E[0]); step1<SGN>(U, E[1]);
    w0.z = E[0].s; w1.z = E[1].s;
    step1<SGN>(U, E[0]); step1<SGN>(U, E[1]);
    w0.w = E[0].s; w1.w = E[1].s;
    o0[0] = w0; o1[0] = w1;

    // Remaining 24 groups of 4 steps (96 steps -> 99 total).
    #pragma unroll 1
    for (int g = 1; g < NSTEPS / 4; ++g) {
        step1<SGN>(U, E[0]); step1<SGN>(U, E[1]);
        w0.x = E[0].s; w1.x = E[1].s;
        step1<SGN>(U, E[0]); step1<SGN>(U, E[1]);
        w0.y = E[0].s; w1.y = E[1].s;
        step1<SGN>(U, E[0]); step1<SGN>(U, E[1]);
        w0.z = E[0].s; w1.z = E[1].s;
        step1<SGN>(U, E[0]); step1<SGN>(U, E[1]);
        w0.w = E[0].s; w1.w = E[1].s;
        o0[g] = w0; o1[g] = w1;
    }
}

__global__ __launch_bounds__(32) void rk4_kernel(
    const float* __restrict__ x, const float* __restrict__ u,
    const float* __restrict__ W1, const float* __restrict__ b1,
    const float* __restrict__ W2, const float* __restrict__ b2,
    float* __restrict__ out, int B)
{
    int i = blockIdx.x * blockDim.x + threadIdx.x;
    int b0 = 2 * i;
    if (b0 >= B) return;

    float2 xv = reinterpret_cast<const float2*>(x)[i];
    float2 uv = reinterpret_cast<const float2*>(u)[i];

    // W1 [2,4] row-major: row 0 multiplies s, row 1 multiplies u.
    float a0 = W1[0], a1 = W1[1], a2 = W1[2], a3 = W1[3];
    float u0 = W1[4], u1 = W1[5], u2 = W1[6], u3 = W1[7];
    float v0 = W2[0], v1 = W2[1], v2 = W2[2], v3 = W2[3];

    float p0 = 0.505f * v0, p1 = 0.505f * v1, p2 = 0.505f * v2, p3 = 0.505f * v3;
    float q0 = 0.495f * v0, q1 = 0.495f * v1, q2 = 0.495f * v2, q3 = 0.495f * v3;
    float bb = b2[0];

    Uni U;
    U.R0 = q0 * a0; U.R1 = q1 * a1; U.R2 = q2 * a2; U.R3 = q3 * a3;
    U.hR0 = 0.5f * U.R0; U.hR1 = 0.5f * U.R1;
    U.hR2 = 0.5f * U.R2; U.hR3 = 0.5f * U.R3;
    U.P = fmaf(p0, a0, fmaf(p1, a1, fmaf(p2, a2, p3 * a3)));
    U.hP = 0.5f * U.P;

    const float us[2] = {uv.x, uv.y};
    const float xs[2] = {xv.x, xv.y};
    El E[2];
    #pragma unroll
    for (int e = 0; e < 2; ++e) {
        float c0 = fmaf(us[e], u0, b1[0]);
        float c1 = fmaf(us[e], u1, b1[1]);
        float c2 = fmaf(us[e], u2, b1[2]);
        float c3 = fmaf(us[e], u3, b1[3]);
        E[e].Qt = bb + fmaf(p0, c0, fmaf(p1, c1, fmaf(p2, c2, p3 * c3)));
        E[e].D0 = q0 * c0; E[e].D1 = q1 * c1;
        E[e].D2 = q2 * c2; E[e].D3 = q3 * c3;
        E[e].s = xs[e];
    }

    float4* o0 = reinterpret_cast<float4*>(out + (size_t)b0 * NSTEPS);
    float4* o1 = reinterpret_cast<float4*>(out + (size_t)(b0 + 1) * NSTEPS);

    // 4-bit sign code of W2 (uniform across all threads -> no divergence).
    int code = (v0 < 0.0f ? 1 : 0) | (v1 < 0.0f ? 2 : 0) |
               (v2 < 0.0f ? 4 : 0) | (v3 < 0.0f ? 8 : 0);

    switch (code) {
        case 0:  run_loop<0 >(U, E, xv, o0, o1); break;
        case 1:  run_loop<1 >(U, E, xv, o0, o1); break;
        case 2:  run_loop<2 >(U, E, xv, o0, o1); break;
        case 3:  run_loop<3 >(U, E, xv, o0, o1); break;
        case 4:  run_loop<4 >(U, E, xv, o0, o1); break;
        case 5:  run_loop<5 >(U, E, xv, o0, o1); break;
        case 6:  run_loop<6 >(U, E, xv, o0, o1); break;
        case 7:  run_loop<7 >(U, E, xv, o0, o1); break;
        case 8:  run_loop<8 >(U, E, xv, o0, o1); break;
        case 9:  run_loop<9 >(U, E, xv, o0, o1); break;
        case 10: run_loop<10>(U, E, xv, o0, o1); break;
        case 11: run_loop<11>(U, E, xv, o0, o1); break;
        case 12: run_loop<12>(U, E, xv, o0, o1); break;
        case 13: run_loop<13>(U, E, xv, o0, o1); break;
        case 14: run_loop<14>(U, E, xv, o0, o1); break;
        case 15: run_loop<15>(U, E, xv, o0, o1); break;
    }
}

extern "C" void kernel_launch(void* const* d_in, const int* in_sizes, int n_in,
                              void* d_out, int out_size)
{
    const float* x  = (const float*)d_in[0];
    const float* u  = (const float*)d_in[1];
    const float* W1 = (const float*)d_in[2];
    const float* b1 = (const float*)d_in[3];
    const float* W2 = (const float*)d_in[4];
    const float* b2 = (const float*)d_in[5];
    float* out = (float*)d_out;
    int B = in_sizes[0];

    int nthreads = B / 2;                // 2 elements per thread (2 scalar chains)
    int threads = 32;                    // 2048 blocks -> 13.8 CTAs/SM, ~3% tail
    int blocks = (nthreads + threads - 1) / threads;
    rk4_kernel<<<blocks, threads>>>(x, u, W1, b1, W2, b2, out, B);
}